// round 10
// baseline (speedup 1.0000x reference)
#include <cuda_runtime.h>
#include <math.h>

#define N_NODES 50000
#define B 64
#define M 32
#define E 128
#define H 8
#define TILE 64

// scratch (allocation-free rule: __device__ globals)
__device__ float g_wv_accum[B * E];
__device__ float g_att2[B * M * H];

// ---------------------------------------------------------------------------
// K0: one block per graph. att2[b][m][h] = mv[b,m,:]@Wa2 + ba2
// ---------------------------------------------------------------------------
__global__ void k0_init(const float* __restrict__ mv,
                        const float* __restrict__ Wa2,
                        const float* __restrict__ ba2) {
    __shared__ float wa2s[E * H];
    int b = blockIdx.x;
    int t = threadIdx.x;
    for (int i = t; i < E * H; i += 256) wa2s[i] = Wa2[i];
    if (t < E) g_wv_accum[b * E + t] = 0.f;
    __syncthreads();

    int m = t >> 3, h = t & 7;
    const float4* row = (const float4*)(mv + (size_t)(b * M + m) * E);
    float s = 0.f;
#pragma unroll 8
    for (int e4 = 0; e4 < 32; e4++) {
        float4 r = row[e4];
        const float* w = wa2s + e4 * 4 * H + h;
        s += r.x * w[0] + r.y * w[H] + r.z * w[2 * H] + r.w * w[3 * H];
    }
    g_att2[(b * M + m) * H + h] = s + ba2[h];
}

// ---------------------------------------------------------------------------
// K1: fused per-tile kernel. 64 nodes/block, 256 threads, 2 CTAs/SM.
// ---------------------------------------------------------------------------
__global__ void __launch_bounds__(256, 2)
k1_main(const float* __restrict__ z, const int* __restrict__ batch,
        const float* __restrict__ mv, const float* __restrict__ bias_mask,
        const float* __restrict__ Wv, const float* __restrict__ bv,
        const float* __restrict__ Wo, const float* __restrict__ bo,
        const float* __restrict__ Wa1, const float* __restrict__ ba1,
        const float* __restrict__ Wh, const float* __restrict__ bh,
        float* __restrict__ out) {
    extern __shared__ float sm[];
    float* Ws    = sm;                    // [128][128] weight, natural [k][c] (Wv then Wo)
    float* zs    = Ws + E * E;            // [64][128] z tile, later output_pre
    float* att1  = zs + TILE * E;         // [64][8]
    float* cofs  = att1 + TILE * H;       // [64][32]
    float* Wa1T  = cofs + TILE * M;       // [8][128] transposed Wa1
    int*   bats  = (int*)(Wa1T + H * E);  // [64]

    const int tid = threadIdx.x;
    const int tilebase = blockIdx.x * TILE;
    const int nvalid = min(TILE, N_NODES - tilebase);

    // --- cooperative loads ---
    {   // Wv natural layout: straight float4 copy (coalesced)
        const float4* src = (const float4*)Wv;
        float4* dst = (float4*)Ws;
        for (int i = tid; i < E * E / 4; i += 256) dst[i] = src[i];
    }
    for (int i4 = tid; i4 < TILE * E / 4; i4 += 256) { // z tile (zero-fill tail)
        int n = i4 >> 5;
        float4 v = make_float4(0.f, 0.f, 0.f, 0.f);
        if (n < nvalid) v = ((const float4*)z)[(size_t)(tilebase + n) * 32 + (i4 & 31)];
        ((float4*)zs)[i4] = v;
    }
    for (int i = tid; i < E * H; i += 256) {           // Wa1T[h][k] = Wa1[k][h]
        int h = i >> 7, k = i & 127;
        Wa1T[h * E + k] = Wa1[k * H + h];
    }
    if (tid < TILE) bats[tid] = (tid < nvalid) ? batch[tilebase + tid] : 0;
    __syncthreads();

    // --- att1 = z @ Wa1 + ba1 (float4 dots against Wa1T rows) ---
    for (int p = tid; p < TILE * H; p += 256) {
        int n = p >> 3, h = p & 7;
        const float4* zr = (const float4*)(zs + n * E);
        const float4* wr = (const float4*)(Wa1T + h * E);
        float s = 0.f;
#pragma unroll 8
        for (int k4 = 0; k4 < 32; k4++) {
            float4 a = zr[k4], w = wr[k4];
            s += a.x * w.x + a.y * w.y + a.z * w.z + a.w * w.w;
        }
        att1[p] = s + ba1[h];
    }

    // thread tile mapping for GEMMs
    const int cg = tid & 31;        // col group: cols 4*cg .. 4*cg+3
    const int nb = (tid >> 5) * 8;  // node base: 8 nodes

    // --- wv GEMM (8x4 tile) + segment accumulation ---
    {
        float acc[8][4];
        float4 bv4 = ((const float4*)bv)[cg];
#pragma unroll
        for (int j = 0; j < 8; j++) {
            acc[j][0] = bv4.x; acc[j][1] = bv4.y; acc[j][2] = bv4.z; acc[j][3] = bv4.w;
        }
        for (int kq = 0; kq < 32; kq++) {
            const float4* wrow = (const float4*)(Ws + kq * 4 * E) + cg;
            float4 w0 = wrow[0];
            float4 w1 = wrow[32];
            float4 w2 = wrow[64];
            float4 w3 = wrow[96];
#pragma unroll
            for (int j = 0; j < 8; j++) {
                float4 zv = ((const float4*)(zs + (nb + j) * E))[kq];
                acc[j][0] += zv.x * w0.x + zv.y * w1.x + zv.z * w2.x + zv.w * w3.x;
                acc[j][1] += zv.x * w0.y + zv.y * w1.y + zv.z * w2.y + zv.w * w3.y;
                acc[j][2] += zv.x * w0.z + zv.y * w1.z + zv.z * w2.z + zv.w * w3.z;
                acc[j][3] += zv.x * w0.w + zv.y * w1.w + zv.z * w2.w + zv.w * w3.w;
            }
        }
        // run-length segment sum over the 8 nodes
        int curg = -1;
        float run[4] = {0.f, 0.f, 0.f, 0.f};
#pragma unroll
        for (int j = 0; j < 8; j++) {
            int node = nb + j;
            int g = (node < nvalid) ? bats[node] : -2;
            if (g != curg) {
                if (curg >= 0) {
#pragma unroll
                    for (int i = 0; i < 4; i++)
                        atomicAdd(&g_wv_accum[curg * E + 4 * cg + i], run[i]);
                }
                curg = g;
                run[0] = run[1] = run[2] = run[3] = 0.f;
            }
            if (g >= 0) {
#pragma unroll
                for (int i = 0; i < 4; i++) run[i] += acc[j][i];
            }
        }
        if (curg >= 0) {
#pragma unroll
            for (int i = 0; i < 4; i++)
                atomicAdd(&g_wv_accum[curg * E + 4 * cg + i], run[i]);
        }
    }
    __syncthreads();

    // --- load Wo -> Ws (overwrite) ---
    {
        const float4* src = (const float4*)Wo;
        float4* dst = (float4*)Ws;
        for (int i = tid; i < E * E / 4; i += 256) dst[i] = src[i];
    }

    // --- attention: 4 threads per node (register-lean version) ---
    {
        const int nl = tid >> 2, q = tid & 3;
        const int g = bats[nl];
        float biasv[8];
#pragma unroll
        for (int mi = 0; mi < 8; mi++)
            biasv[mi] = (bias_mask[g * M + q * 8 + mi] - 1.f) * 1e9f;
        float w[8];
        float bh0 = bh[0];
#pragma unroll
        for (int mi = 0; mi < 8; mi++) w[mi] = bh0;
        const float* a2 = g_att2 + g * M * H;
#pragma unroll
        for (int h = 0; h < H; h++) {
            float a1h = att1[nl * H + h];       // smem broadcast, no reg array
            float lh[8];
            float mx = -3.4e38f;
#pragma unroll
            for (int mi = 0; mi < 8; mi++) {
                float l = a1h + a2[(q * 8 + mi) * H + h];
                l = (l >= 0.f) ? l : 0.01f * l;   // leaky_relu
                l += biasv[mi];
                lh[mi] = l;
                mx = fmaxf(mx, l);
            }
            mx = fmaxf(mx, __shfl_xor_sync(0xffffffffu, mx, 1));
            mx = fmaxf(mx, __shfl_xor_sync(0xffffffffu, mx, 2));
            float s = 0.f;
#pragma unroll
            for (int mi = 0; mi < 8; mi++) { lh[mi] = __expf(lh[mi] - mx); s += lh[mi]; }
            s += __shfl_xor_sync(0xffffffffu, s, 1);
            s += __shfl_xor_sync(0xffffffffu, s, 2);
            float whh = Wh[h];
            float invs = 1.f / s;
#pragma unroll
            for (int mi = 0; mi < 8; mi++) w[mi] += (lh[mi] * invs) * whh;
        }
        // second softmax over slots
        float mx2 = -3.4e38f;
#pragma unroll
        for (int mi = 0; mi < 8; mi++) mx2 = fmaxf(mx2, w[mi]);
        mx2 = fmaxf(mx2, __shfl_xor_sync(0xffffffffu, mx2, 1));
        mx2 = fmaxf(mx2, __shfl_xor_sync(0xffffffffu, mx2, 2));
        float s2 = 0.f;
#pragma unroll
        for (int mi = 0; mi < 8; mi++) { w[mi] = __expf(w[mi] - mx2); s2 += w[mi]; }
        s2 += __shfl_xor_sync(0xffffffffu, s2, 1);
        s2 += __shfl_xor_sync(0xffffffffu, s2, 2);
        float inv2 = 1.f / s2;
#pragma unroll
        for (int mi = 0; mi < 8; mi++) cofs[nl * M + q * 8 + mi] = w[mi] * inv2;
        __syncwarp();

        // output_pre = coefs @ mv[g] in two 16-col chunks (cap register peak)
        const float* mvbase = mv + (size_t)g * M * E + q * 32;
#pragma unroll
        for (int ch = 0; ch < 2; ch++) {
            float op[16];
#pragma unroll
            for (int i = 0; i < 16; i++) op[i] = 0.f;
            const float4* mvc = (const float4*)(mvbase + ch * 16);
#pragma unroll 4
            for (int m = 0; m < M; m++) {
                float cm = cofs[nl * M + m];
                const float4* row = mvc + m * 32;   // row stride E = 32 float4
#pragma unroll
                for (int i = 0; i < 4; i++) {
                    float4 v = row[i];
                    op[i * 4 + 0] += cm * v.x;
                    op[i * 4 + 1] += cm * v.y;
                    op[i * 4 + 2] += cm * v.z;
                    op[i * 4 + 3] += cm * v.w;
                }
            }
            float4* zr = (float4*)(zs + nl * E + q * 32 + ch * 16);
#pragma unroll
            for (int i = 0; i < 4; i++)
                zr[i] = make_float4(op[i * 4], op[i * 4 + 1],
                                    op[i * 4 + 2], op[i * 4 + 3]);
        }
    }
    __syncthreads();

    // --- out = output_pre @ Wo + bo (8x4 tile, float4 store) ---
    {
        float acc[8][4];
        float4 bo4 = ((const float4*)bo)[cg];
#pragma unroll
        for (int j = 0; j < 8; j++) {
            acc[j][0] = bo4.x; acc[j][1] = bo4.y; acc[j][2] = bo4.z; acc[j][3] = bo4.w;
        }
        for (int kq = 0; kq < 32; kq++) {
            const float4* wrow = (const float4*)(Ws + kq * 4 * E) + cg;
            float4 w0 = wrow[0];
            float4 w1 = wrow[32];
            float4 w2 = wrow[64];
            float4 w3 = wrow[96];
#pragma unroll
            for (int j = 0; j < 8; j++) {
                float4 zv = ((const float4*)(zs + (nb + j) * E))[kq];
                acc[j][0] += zv.x * w0.x + zv.y * w1.x + zv.z * w2.x + zv.w * w3.x;
                acc[j][1] += zv.x * w0.y + zv.y * w1.y + zv.z * w2.y + zv.w * w3.y;
                acc[j][2] += zv.x * w0.z + zv.y * w1.z + zv.z * w2.z + zv.w * w3.z;
                acc[j][3] += zv.x * w0.w + zv.y * w1.w + zv.z * w2.w + zv.w * w3.w;
            }
        }
#pragma unroll
        for (int j = 0; j < 8; j++) {
            if (nb + j < nvalid)
                ((float4*)(out + (size_t)(tilebase + nb + j) * E))[cg] =
                    make_float4(acc[j][0], acc[j][1], acc[j][2], acc[j][3]);
        }
    }
}

// ---------------------------------------------------------------------------
// K2: state updates + arange output
// out layout: [output N*E | arange N | new_mv B*M*E | new_write_mask | new_bias_mask]
// ---------------------------------------------------------------------------
__global__ void k2_final(const float* __restrict__ mv,
                         const float* __restrict__ write_mask,
                         const float* __restrict__ bias_mask,
                         float* __restrict__ out) {
    int idx = blockIdx.x * blockDim.x + threadIdx.x;
    const size_t OUT1 = (size_t)N_NODES * E;
    const size_t OUT2 = OUT1 + N_NODES;
    const size_t OUT3 = OUT2 + (size_t)B * M * E;
    const size_t OUT4 = OUT3 + (size_t)B * M;
    if (idx < B * M * E) {
        int b = idx >> 12;
        int m = (idx >> 7) & 31;
        float wvv = tanhf(g_wv_accum[b * E + (idx & 127)]);
        out[OUT2 + idx] = mv[idx] + wvv * write_mask[b * M + m];
    }
    if (idx < B * M) {
        int b = idx >> 5, m = idx & 31;
        out[OUT3 + idx] = write_mask[b * M + ((m + 31) & 31)];        // roll(+1)
        out[OUT4 + idx] = fminf(bias_mask[idx] + write_mask[idx], 1.f);
    }
    if (idx < N_NODES) out[OUT1 + idx] = (float)idx;                  // arange
}

// ---------------------------------------------------------------------------
extern "C" void kernel_launch(void* const* d_in, const int* in_sizes, int n_in,
                              void* d_out, int out_size) {
    const float* z     = (const float*)d_in[0];
    const int*   batch = (const int*)d_in[1];
    const float* mv    = (const float*)d_in[2];
    const float* wm    = (const float*)d_in[3];
    const float* bm    = (const float*)d_in[4];
    const float* Wv    = (const float*)d_in[5];
    const float* bv    = (const float*)d_in[6];
    const float* Wo    = (const float*)d_in[7];
    const float* bo    = (const float*)d_in[8];
    const float* Wa1   = (const float*)d_in[9];
    const float* ba1   = (const float*)d_in[10];
    const float* Wa2   = (const float*)d_in[11];
    const float* ba2   = (const float*)d_in[12];
    const float* Wh    = (const float*)d_in[13];
    const float* bh    = (const float*)d_in[14];
    float* out = (float*)d_out;

    const int SMEM_BYTES =
        (E * E + TILE * E + TILE * H + TILE * M + H * E + TILE) * 4;
    cudaFuncSetAttribute(k1_main, cudaFuncAttributeMaxDynamicSharedMemorySize,
                         SMEM_BYTES);

    k0_init<<<B, 256>>>(mv, Wa2, ba2);

    int nblocks = (N_NODES + TILE - 1) / TILE;
    k1_main<<<nblocks, 256, SMEM_BYTES>>>(z, batch, mv, bm, Wv, bv, Wo, bo,
                                          Wa1, ba1, Wh, bh, out);

    k2_final<<<(B * M * E + 255) / 256, 256>>>(mv, wm, bm, out);
}

// round 11
// speedup vs baseline: 1.0148x; 1.0148x over previous
#include <cuda_runtime.h>
#include <math.h>

#define N_NODES 50000
#define B 64
#define M 32
#define E 128
#define H 8
#define TILE 64

typedef unsigned long long u64;

// packed fp32x2 helpers (sm_103a FFMA2 — exact IEEE fp32 per lane)
__device__ __forceinline__ u64 pack2(float lo, float hi) {
    u64 r; asm("mov.b64 %0, {%1, %2};" : "=l"(r) : "f"(lo), "f"(hi)); return r;
}
__device__ __forceinline__ void fma2(u64& d, u64 a, u64 b) {
    asm("fma.rn.f32x2 %0, %1, %2, %0;" : "+l"(d) : "l"(a), "l"(b));
}
__device__ __forceinline__ float2 unpack2(u64 v) {
    float2 r; asm("mov.b64 {%0, %1}, %2;" : "=f"(r.x), "=f"(r.y) : "l"(v)); return r;
}

// scratch (allocation-free rule: __device__ globals)
__device__ float g_wv_accum[B * E];
__device__ float g_att2[B * M * H];

// ---------------------------------------------------------------------------
// K0: grid = B*M blocks, 256 threads (8 warps = 8 heads). Warp h computes
//     att2[bm][h] = mv[bm,:] @ Wa2[:,h] via lane-split float4 + shfl reduce.
//     First 32 blocks also zero g_wv_accum.
// ---------------------------------------------------------------------------
__global__ void k0_init(const float* __restrict__ mv,
                        const float* __restrict__ Wa2,
                        const float* __restrict__ ba2) {
    int bm = blockIdx.x;                 // 0 .. B*M-1
    int h = threadIdx.x >> 5;
    int lane = threadIdx.x & 31;
    if (bm < 32) g_wv_accum[bm * 256 + threadIdx.x] = 0.f;   // 32*256 = B*E

    float4 r = ((const float4*)(mv + (size_t)bm * E))[lane];
    const float* w = Wa2 + lane * 4 * H + h;
    float s = r.x * w[0] + r.y * w[H] + r.z * w[2 * H] + r.w * w[3 * H];
#pragma unroll
    for (int off = 16; off > 0; off >>= 1)
        s += __shfl_down_sync(0xffffffffu, s, off);
    if (lane == 0) g_att2[bm * H + h] = s + ba2[h];
}

// ---------------------------------------------------------------------------
// K1: fused per-tile kernel. 64 nodes/block, 256 threads, 2 CTAs/SM.
//     GEMMs use packed f32x2 FMA (column-paired, weights pre-paired in smem).
// ---------------------------------------------------------------------------
__global__ void __launch_bounds__(256, 2)
k1_main(const float* __restrict__ z, const int* __restrict__ batch,
        const float* __restrict__ mv, const float* __restrict__ bias_mask,
        const float* __restrict__ Wv, const float* __restrict__ bv,
        const float* __restrict__ Wo, const float* __restrict__ bo,
        const float* __restrict__ Wa1, const float* __restrict__ ba1,
        const float* __restrict__ Wh, const float* __restrict__ bh,
        float* __restrict__ out) {
    extern __shared__ float sm[];
    float* Ws    = sm;                    // [128][128] weight, natural [k][c] (Wv then Wo)
    float* zs    = Ws + E * E;            // [64][128] z tile, later output_pre
    float* att1  = zs + TILE * E;         // [64][8]
    float* cofs  = att1 + TILE * H;       // [64][32]
    float* Wa1T  = cofs + TILE * M;       // [8][128] transposed Wa1
    int*   bats  = (int*)(Wa1T + H * E);  // [64]

    const int tid = threadIdx.x;
    const int tilebase = blockIdx.x * TILE;
    const int nvalid = min(TILE, N_NODES - tilebase);

    // --- cooperative loads ---
    {   // Wv natural layout: straight float4 copy (coalesced)
        const float4* src = (const float4*)Wv;
        float4* dst = (float4*)Ws;
        for (int i = tid; i < E * E / 4; i += 256) dst[i] = src[i];
    }
    for (int i4 = tid; i4 < TILE * E / 4; i4 += 256) { // z tile (zero-fill tail)
        int n = i4 >> 5;
        float4 v = make_float4(0.f, 0.f, 0.f, 0.f);
        if (n < nvalid) v = ((const float4*)z)[(size_t)(tilebase + n) * 32 + (i4 & 31)];
        ((float4*)zs)[i4] = v;
    }
    for (int i = tid; i < E * H; i += 256) {           // Wa1T[h][k] = Wa1[k][h]
        int h = i >> 7, k = i & 127;
        Wa1T[h * E + k] = Wa1[k * H + h];
    }
    if (tid < TILE) bats[tid] = (tid < nvalid) ? batch[tilebase + tid] : 0;
    __syncthreads();

    // --- att1 = z @ Wa1 + ba1 (float4 dots against Wa1T rows) ---
    for (int p = tid; p < TILE * H; p += 256) {
        int n = p >> 3, h = p & 7;
        const float4* zr = (const float4*)(zs + n * E);
        const float4* wr = (const float4*)(Wa1T + h * E);
        float s = 0.f;
#pragma unroll 8
        for (int k4 = 0; k4 < 32; k4++) {
            float4 a = zr[k4], w = wr[k4];
            s += a.x * w.x + a.y * w.y + a.z * w.z + a.w * w.w;
        }
        att1[p] = s + ba1[h];
    }

    // thread tile mapping for GEMMs
    const int cg = tid & 31;        // col group: cols 4*cg .. 4*cg+3
    const int nb = (tid >> 5) * 8;  // node base: 8 nodes

    // --- wv GEMM (8 nodes x 2 col-pairs, f32x2) + segment accumulation ---
    {
        u64 acc2[8][2];
        ulonglong2 bv2 = ((const ulonglong2*)bv)[cg];
#pragma unroll
        for (int j = 0; j < 8; j++) { acc2[j][0] = bv2.x; acc2[j][1] = bv2.y; }
        for (int kq = 0; kq < 32; kq++) {
            const ulonglong2* wrow = (const ulonglong2*)(Ws + kq * 4 * E) + cg;
            ulonglong2 w0 = wrow[0];
            ulonglong2 w1 = wrow[32];
            ulonglong2 w2 = wrow[64];
            ulonglong2 w3 = wrow[96];
#pragma unroll
            for (int j = 0; j < 8; j++) {
                float4 zv = ((const float4*)(zs + (nb + j) * E))[kq];
                u64 zx = pack2(zv.x, zv.x), zy = pack2(zv.y, zv.y);
                u64 zz = pack2(zv.z, zv.z), zw = pack2(zv.w, zv.w);
                fma2(acc2[j][0], zx, w0.x); fma2(acc2[j][1], zx, w0.y);
                fma2(acc2[j][0], zy, w1.x); fma2(acc2[j][1], zy, w1.y);
                fma2(acc2[j][0], zz, w2.x); fma2(acc2[j][1], zz, w2.y);
                fma2(acc2[j][0], zw, w3.x); fma2(acc2[j][1], zw, w3.y);
            }
        }
        // run-length segment sum over the 8 nodes
        int curg = -1;
        float run[4] = {0.f, 0.f, 0.f, 0.f};
#pragma unroll
        for (int j = 0; j < 8; j++) {
            int node = nb + j;
            int g = (node < nvalid) ? bats[node] : -2;
            if (g != curg) {
                if (curg >= 0) {
#pragma unroll
                    for (int i = 0; i < 4; i++)
                        atomicAdd(&g_wv_accum[curg * E + 4 * cg + i], run[i]);
                }
                curg = g;
                run[0] = run[1] = run[2] = run[3] = 0.f;
            }
            if (g >= 0) {
                float2 a0 = unpack2(acc2[j][0]);
                float2 a1 = unpack2(acc2[j][1]);
                run[0] += a0.x; run[1] += a0.y; run[2] += a1.x; run[3] += a1.y;
            }
        }
        if (curg >= 0) {
#pragma unroll
            for (int i = 0; i < 4; i++)
                atomicAdd(&g_wv_accum[curg * E + 4 * cg + i], run[i]);
        }
    }
    __syncthreads();

    // --- load Wo -> Ws (overwrite) ---
    {
        const float4* src = (const float4*)Wo;
        float4* dst = (float4*)Ws;
        for (int i = tid; i < E * E / 4; i += 256) dst[i] = src[i];
    }

    // --- attention: 4 threads per node ---
    {
        const int nl = tid >> 2, q = tid & 3;
        const int g = bats[nl];
        float biasv[8];
#pragma unroll
        for (int mi = 0; mi < 8; mi++)
            biasv[mi] = (bias_mask[g * M + q * 8 + mi] - 1.f) * 1e9f;
        float w[8];
        float bh0 = bh[0];
#pragma unroll
        for (int mi = 0; mi < 8; mi++) w[mi] = bh0;
        const float* a2 = g_att2 + g * M * H;
#pragma unroll
        for (int h = 0; h < H; h++) {
            float a1h = att1[nl * H + h];
            float lh[8];
            float mx = -3.4e38f;
#pragma unroll
            for (int mi = 0; mi < 8; mi++) {
                float l = a1h + a2[(q * 8 + mi) * H + h];
                l = (l >= 0.f) ? l : 0.01f * l;   // leaky_relu
                l += biasv[mi];
                lh[mi] = l;
                mx = fmaxf(mx, l);
            }
            mx = fmaxf(mx, __shfl_xor_sync(0xffffffffu, mx, 1));
            mx = fmaxf(mx, __shfl_xor_sync(0xffffffffu, mx, 2));
            float s = 0.f;
#pragma unroll
            for (int mi = 0; mi < 8; mi++) { lh[mi] = __expf(lh[mi] - mx); s += lh[mi]; }
            s += __shfl_xor_sync(0xffffffffu, s, 1);
            s += __shfl_xor_sync(0xffffffffu, s, 2);
            float whh = Wh[h];
            float invs = 1.f / s;
#pragma unroll
            for (int mi = 0; mi < 8; mi++) w[mi] += (lh[mi] * invs) * whh;
        }
        // second softmax over slots
        float mx2 = -3.4e38f;
#pragma unroll
        for (int mi = 0; mi < 8; mi++) mx2 = fmaxf(mx2, w[mi]);
        mx2 = fmaxf(mx2, __shfl_xor_sync(0xffffffffu, mx2, 1));
        mx2 = fmaxf(mx2, __shfl_xor_sync(0xffffffffu, mx2, 2));
        float s2 = 0.f;
#pragma unroll
        for (int mi = 0; mi < 8; mi++) { w[mi] = __expf(w[mi] - mx2); s2 += w[mi]; }
        s2 += __shfl_xor_sync(0xffffffffu, s2, 1);
        s2 += __shfl_xor_sync(0xffffffffu, s2, 2);
        float inv2 = 1.f / s2;
#pragma unroll
        for (int mi = 0; mi < 8; mi++) cofs[nl * M + q * 8 + mi] = w[mi] * inv2;
        __syncwarp();

        // output_pre = coefs @ mv[g] in two 16-col chunks (f32x2)
        const float* mvbase = mv + (size_t)g * M * E + q * 32;
#pragma unroll
        for (int ch = 0; ch < 2; ch++) {
            u64 op2[8];
#pragma unroll
            for (int i = 0; i < 8; i++) op2[i] = 0ull;
            const ulonglong2* mvc = (const ulonglong2*)(mvbase + ch * 16);
#pragma unroll 4
            for (int m = 0; m < M; m++) {
                float cm = cofs[nl * M + m];
                u64 cm2 = pack2(cm, cm);
                const ulonglong2* row = mvc + m * 32;   // row stride E = 32 ull2
#pragma unroll
                for (int i = 0; i < 4; i++) {
                    ulonglong2 v = row[i];
                    fma2(op2[i * 2 + 0], cm2, v.x);
                    fma2(op2[i * 2 + 1], cm2, v.y);
                }
            }
            ulonglong2* zr = (ulonglong2*)(zs + nl * E + q * 32 + ch * 16);
#pragma unroll
            for (int i = 0; i < 4; i++) {
                ulonglong2 st; st.x = op2[i * 2]; st.y = op2[i * 2 + 1];
                zr[i] = st;
            }
        }
    }
    __syncthreads();

    // --- out = output_pre @ Wo + bo (f32x2, ulonglong2 store) ---
    {
        u64 acc2[8][2];
        ulonglong2 bo2 = ((const ulonglong2*)bo)[cg];
#pragma unroll
        for (int j = 0; j < 8; j++) { acc2[j][0] = bo2.x; acc2[j][1] = bo2.y; }
        for (int kq = 0; kq < 32; kq++) {
            const ulonglong2* wrow = (const ulonglong2*)(Ws + kq * 4 * E) + cg;
            ulonglong2 w0 = wrow[0];
            ulonglong2 w1 = wrow[32];
            ulonglong2 w2 = wrow[64];
            ulonglong2 w3 = wrow[96];
#pragma unroll
            for (int j = 0; j < 8; j++) {
                float4 zv = ((const float4*)(zs + (nb + j) * E))[kq];
                u64 zx = pack2(zv.x, zv.x), zy = pack2(zv.y, zv.y);
                u64 zz = pack2(zv.z, zv.z), zw = pack2(zv.w, zv.w);
                fma2(acc2[j][0], zx, w0.x); fma2(acc2[j][1], zx, w0.y);
                fma2(acc2[j][0], zy, w1.x); fma2(acc2[j][1], zy, w1.y);
                fma2(acc2[j][0], zz, w2.x); fma2(acc2[j][1], zz, w2.y);
                fma2(acc2[j][0], zw, w3.x); fma2(acc2[j][1], zw, w3.y);
            }
        }
#pragma unroll
        for (int j = 0; j < 8; j++) {
            if (nb + j < nvalid) {
                ulonglong2 st; st.x = acc2[j][0]; st.y = acc2[j][1];
                ((ulonglong2*)(out + (size_t)(tilebase + nb + j) * E))[cg] = st;
            }
        }
    }
}

// ---------------------------------------------------------------------------
// K2: state updates + arange output
// out layout: [output N*E | arange N | new_mv B*M*E | new_write_mask | new_bias_mask]
// ---------------------------------------------------------------------------
__global__ void k2_final(const float* __restrict__ mv,
                         const float* __restrict__ write_mask,
                         const float* __restrict__ bias_mask,
                         float* __restrict__ out) {
    int idx = blockIdx.x * blockDim.x + threadIdx.x;
    const size_t OUT1 = (size_t)N_NODES * E;
    const size_t OUT2 = OUT1 + N_NODES;
    const size_t OUT3 = OUT2 + (size_t)B * M * E;
    const size_t OUT4 = OUT3 + (size_t)B * M;
    if (idx < B * M * E) {
        int b = idx >> 12;
        int m = (idx >> 7) & 31;
        float wvv = tanhf(g_wv_accum[b * E + (idx & 127)]);
        out[OUT2 + idx] = mv[idx] + wvv * write_mask[b * M + m];
    }
    if (idx < B * M) {
        int b = idx >> 5, m = idx & 31;
        out[OUT3 + idx] = write_mask[b * M + ((m + 31) & 31)];        // roll(+1)
        out[OUT4 + idx] = fminf(bias_mask[idx] + write_mask[idx], 1.f);
    }
    if (idx < N_NODES) out[OUT1 + idx] = (float)idx;                  // arange
}

// ---------------------------------------------------------------------------
extern "C" void kernel_launch(void* const* d_in, const int* in_sizes, int n_in,
                              void* d_out, int out_size) {
    const float* z     = (const float*)d_in[0];
    const int*   batch = (const int*)d_in[1];
    const float* mv    = (const float*)d_in[2];
    const float* wm    = (const float*)d_in[3];
    const float* bm    = (const float*)d_in[4];
    const float* Wv    = (const float*)d_in[5];
    const float* bv    = (const float*)d_in[6];
    const float* Wo    = (const float*)d_in[7];
    const float* bo    = (const float*)d_in[8];
    const float* Wa1   = (const float*)d_in[9];
    const float* ba1   = (const float*)d_in[10];
    const float* Wa2   = (const float*)d_in[11];
    const float* ba2   = (const float*)d_in[12];
    const float* Wh    = (const float*)d_in[13];
    const float* bh    = (const float*)d_in[14];
    float* out = (float*)d_out;

    const int SMEM_BYTES =
        (E * E + TILE * E + TILE * H + TILE * M + H * E + TILE) * 4;
    cudaFuncSetAttribute(k1_main, cudaFuncAttributeMaxDynamicSharedMemorySize,
                         SMEM_BYTES);

    k0_init<<<B * M, 256>>>(mv, Wa2, ba2);

    int nblocks = (N_NODES + TILE - 1) / TILE;
    k1_main<<<nblocks, 256, SMEM_BYTES>>>(z, batch, mv, bm, Wv, bv, Wo, bo,
                                          Wa1, ba1, Wh, bh, out);

    k2_final<<<(B * M * E + 255) / 256, 256>>>(mv, wm, bm, out);
}

// round 12
// speedup vs baseline: 2.1846x; 2.1528x over previous
#include <cuda_runtime.h>
#include <math.h>

#define N_NODES 50000
#define B 64
#define M 32
#define E 128
#define H 8

// scratch (allocation-free rule: __device__ globals)
__device__ float g_zsum[B * E];
__device__ float g_cnt[B];
__device__ float g_wv[B * E];        // tanh(write_values)
__device__ float g_att2[B * M * H];
__device__ float g_mvwo[B * M * E];  // mv @ Wo

// ---------------------------------------------------------------------------
// kzero: clear accumulators
// ---------------------------------------------------------------------------
__global__ void kzero() {
    int i = blockIdx.x * 256 + threadIdx.x;
    if (i < B * E) g_zsum[i] = 0.f;
    if (i < B) g_cnt[i] = 0.f;
}

// ---------------------------------------------------------------------------
// kS: zsum[g] = segment_sum(z), cnt[g] = node count. 256 nodes/block.
//     thread = (half, c): column c over 128 nodes, run-length + atomics.
// ---------------------------------------------------------------------------
__global__ void kS(const float* __restrict__ z, const int* __restrict__ batch) {
    __shared__ int bats[256];
    const int tid = threadIdx.x;
    const int nb0 = blockIdx.x * 256;
    const int nvalid = min(256, N_NODES - nb0);
    bats[tid] = (tid < nvalid) ? batch[nb0 + tid] : -1;
    __syncthreads();

    const int c = tid & 127;
    const int base = (tid >> 7) * 128;
    float run = 0.f, runc = 0.f;
    int curg = -1;
#pragma unroll 4
    for (int j = 0; j < 128; j++) {
        int node = base + j;
        int g = bats[node];
        if (g != curg) {
            if (curg >= 0) {
                atomicAdd(&g_zsum[curg * E + c], run);
                if (c == 0) atomicAdd(&g_cnt[curg], runc);
            }
            curg = g; run = 0.f; runc = 0.f;
        }
        if (g >= 0) {
            run += z[(size_t)(nb0 + node) * E + c];
            runc += 1.f;
        }
    }
    if (curg >= 0) {
        atomicAdd(&g_zsum[curg * E + c], run);
        if (c == 0) atomicAdd(&g_cnt[curg], runc);
    }
}

// ---------------------------------------------------------------------------
// kP: one block per graph b. Computes:
//   g_mvwo[b] = mv[b] @ Wo          (32x128 @ 128x128)
//   g_att2[b] = mv[b] @ Wa2 + ba2   (32x8)
//   g_wv[b]   = tanh(zsum[b] @ Wv + cnt_b * bv)
// ---------------------------------------------------------------------------
__global__ void __launch_bounds__(256, 1)
kP(const float* __restrict__ mv, const float* __restrict__ Wo,
   const float* __restrict__ Wa2, const float* __restrict__ ba2,
   const float* __restrict__ Wv, const float* __restrict__ bv) {
    extern __shared__ float sp[];
    float* Wos = sp;            // [128][128]
    float* mvs = sp + E * E;    // [32][128]
    const int b = blockIdx.x, tid = threadIdx.x;

    for (int i = tid; i < E * E / 4; i += 256)
        ((float4*)Wos)[i] = ((const float4*)Wo)[i];
    for (int i = tid; i < M * E / 4; i += 256)
        ((float4*)mvs)[i] = ((const float4*)(mv + (size_t)b * M * E))[i];
    __syncthreads();

    // mvWo: thread tile 4 m-rows x 4 cols
    {
        const int cg = tid & 31;
        const int mb = (tid >> 5) * 4;
        float acc[4][4];
#pragma unroll
        for (int j = 0; j < 4; j++)
            acc[j][0] = acc[j][1] = acc[j][2] = acc[j][3] = 0.f;
        for (int kq = 0; kq < 32; kq++) {
            const float4* wrow = (const float4*)(Wos + kq * 4 * E) + cg;
            float4 w0 = wrow[0], w1 = wrow[32], w2 = wrow[64], w3 = wrow[96];
#pragma unroll
            for (int j = 0; j < 4; j++) {
                float4 zv = ((const float4*)(mvs + (mb + j) * E))[kq];
                acc[j][0] += zv.x * w0.x + zv.y * w1.x + zv.z * w2.x + zv.w * w3.x;
                acc[j][1] += zv.x * w0.y + zv.y * w1.y + zv.z * w2.y + zv.w * w3.y;
                acc[j][2] += zv.x * w0.z + zv.y * w1.z + zv.z * w2.z + zv.w * w3.z;
                acc[j][3] += zv.x * w0.w + zv.y * w1.w + zv.z * w2.w + zv.w * w3.w;
            }
        }
#pragma unroll
        for (int j = 0; j < 4; j++)
            ((float4*)(g_mvwo + (size_t)b * M * E + (mb + j) * E))[cg] =
                make_float4(acc[j][0], acc[j][1], acc[j][2], acc[j][3]);
    }

    // att2: thread = (m, h)
    {
        const int m = tid >> 3, h = tid & 7;
        const float* row = mvs + m * E;
        float s = 0.f;
#pragma unroll 8
        for (int e = 0; e < E; e++) s += row[e] * Wa2[e * H + h];
        g_att2[(b * M + m) * H + h] = s + ba2[h];
    }

    // write_values: threads 0..127, col c
    if (tid < E) {
        float s = g_cnt[b] * bv[tid];
        const float* zs = g_zsum + b * E;
#pragma unroll 8
        for (int k = 0; k < E; k++) s += zs[k] * Wv[k * E + tid];
        g_wv[b * E + tid] = tanhf(s);
    }
}

// ---------------------------------------------------------------------------
// kATT: one warp per node. att1 inline, two softmaxes (warp shfl),
//       einsum over mvWo, +bo, write final output. 8 nodes/block.
// ---------------------------------------------------------------------------
__global__ void __launch_bounds__(256)
kATT(const float* __restrict__ z, const int* __restrict__ batch,
     const float* __restrict__ bias_mask,
     const float* __restrict__ Wa1, const float* __restrict__ ba1,
     const float* __restrict__ Wh, const float* __restrict__ bh,
     const float* __restrict__ bo, float* __restrict__ out) {
    __shared__ float wa1t[H * E];   // [h][k]
    const int tid = threadIdx.x;
    for (int i = tid; i < E * H; i += 256) {
        int h = i >> 7, k = i & 127;
        wa1t[h * E + k] = Wa1[k * H + h];
    }
    __syncthreads();

    const int lane = tid & 31;
    const int n = blockIdx.x * 8 + (tid >> 5);
    const int g = batch[n];   // grid covers exactly 50000 (6250*8)

    // att1 = z[n] @ Wa1 + ba1 (lane-parallel partial + butterfly reduce)
    float4 z4 = ((const float4*)(z + (size_t)n * E))[lane];
    float a1[H];
#pragma unroll
    for (int h = 0; h < H; h++) {
        float4 w4 = ((const float4*)(wa1t + h * E))[lane];
        float p = z4.x * w4.x + z4.y * w4.y + z4.z * w4.z + z4.w * w4.w;
#pragma unroll
        for (int off = 16; off > 0; off >>= 1)
            p += __shfl_xor_sync(0xffffffffu, p, off);
        a1[h] = p + ba1[h];
    }

    // lane m owns slot m
    float a2v[8];
    {
        const float4* a2p = (const float4*)(g_att2 + ((size_t)g * M + lane) * H);
        float4 x = a2p[0], y = a2p[1];
        a2v[0] = x.x; a2v[1] = x.y; a2v[2] = x.z; a2v[3] = x.w;
        a2v[4] = y.x; a2v[5] = y.y; a2v[6] = y.z; a2v[7] = y.w;
    }
    float biasm = (bias_mask[g * M + lane] - 1.f) * 1e9f;
    float whv = (lane < H) ? Wh[lane] : 0.f;

    float w = bh[0];
#pragma unroll
    for (int h = 0; h < H; h++) {
        float l = a1[h] + a2v[h];
        l = (l >= 0.f) ? l : 0.01f * l;   // leaky_relu
        l += biasm;
        float mx = l;
#pragma unroll
        for (int off = 16; off > 0; off >>= 1)
            mx = fmaxf(mx, __shfl_xor_sync(0xffffffffu, mx, off));
        float e = __expf(l - mx);
        float s = e;
#pragma unroll
        for (int off = 16; off > 0; off >>= 1)
            s += __shfl_xor_sync(0xffffffffu, s, off);
        w += (e / s) * __shfl_sync(0xffffffffu, whv, h);
    }

    // second softmax over slots (lanes)
    float mx2 = w;
#pragma unroll
    for (int off = 16; off > 0; off >>= 1)
        mx2 = fmaxf(mx2, __shfl_xor_sync(0xffffffffu, mx2, off));
    float e2 = __expf(w - mx2);
    float s2 = e2;
#pragma unroll
    for (int off = 16; off > 0; off >>= 1)
        s2 += __shfl_xor_sync(0xffffffffu, s2, off);
    float c = e2 / s2;

    // out[n] = sum_m c_m * mvWo[g][m] + bo   (lane owns 4 cols)
    float4 acc = make_float4(0.f, 0.f, 0.f, 0.f);
    const float4* mw = (const float4*)(g_mvwo + (size_t)g * M * E);
#pragma unroll 8
    for (int m = 0; m < M; m++) {
        float cm = __shfl_sync(0xffffffffu, c, m);
        float4 v = mw[m * 32 + lane];
        acc.x += cm * v.x; acc.y += cm * v.y;
        acc.z += cm * v.z; acc.w += cm * v.w;
    }
    float4 bo4 = ((const float4*)bo)[lane];
    acc.x += bo4.x; acc.y += bo4.y; acc.z += bo4.z; acc.w += bo4.w;
    ((float4*)(out + (size_t)n * E))[lane] = acc;
}

// ---------------------------------------------------------------------------
// k2: state updates + arange
// out layout: [output N*E | arange N | new_mv B*M*E | new_write_mask | new_bias_mask]
// ---------------------------------------------------------------------------
__global__ void k2_final(const float* __restrict__ mv,
                         const float* __restrict__ write_mask,
                         const float* __restrict__ bias_mask,
                         float* __restrict__ out) {
    int idx = blockIdx.x * blockDim.x + threadIdx.x;
    const size_t OUT1 = (size_t)N_NODES * E;
    const size_t OUT2 = OUT1 + N_NODES;
    const size_t OUT3 = OUT2 + (size_t)B * M * E;
    const size_t OUT4 = OUT3 + (size_t)B * M;
    if (idx < B * M * E) {
        int b = idx >> 12;
        int m = (idx >> 7) & 31;
        out[OUT2 + idx] = mv[idx] + g_wv[b * E + (idx & 127)] * write_mask[b * M + m];
    }
    if (idx < B * M) {
        int b = idx >> 5, m = idx & 31;
        out[OUT3 + idx] = write_mask[b * M + ((m + 31) & 31)];        // roll(+1)
        out[OUT4 + idx] = fminf(bias_mask[idx] + write_mask[idx], 1.f);
    }
    if (idx < N_NODES) out[OUT1 + idx] = (float)idx;                  // arange
}

// ---------------------------------------------------------------------------
extern "C" void kernel_launch(void* const* d_in, const int* in_sizes, int n_in,
                              void* d_out, int out_size) {
    const float* z     = (const float*)d_in[0];
    const int*   batch = (const int*)d_in[1];
    const float* mv    = (const float*)d_in[2];
    const float* wm    = (const float*)d_in[3];
    const float* bm    = (const float*)d_in[4];
    const float* Wv    = (const float*)d_in[5];
    const float* bv    = (const float*)d_in[6];
    const float* Wo    = (const float*)d_in[7];
    const float* bo    = (const float*)d_in[8];
    const float* Wa1   = (const float*)d_in[9];
    const float* ba1   = (const float*)d_in[10];
    const float* Wa2   = (const float*)d_in[11];
    const float* ba2   = (const float*)d_in[12];
    const float* Wh    = (const float*)d_in[13];
    const float* bh    = (const float*)d_in[14];
    float* out = (float*)d_out;

    const int SMEM_P = (E * E + M * E) * 4;   // 80 KB
    cudaFuncSetAttribute(kP, cudaFuncAttributeMaxDynamicSharedMemorySize, SMEM_P);

    kzero<<<32, 256>>>();
    kS<<<(N_NODES + 255) / 256, 256>>>(z, batch);
    kP<<<B, 256, SMEM_P>>>(mv, Wo, Wa2, ba2, Wv, bv);
    kATT<<<N_NODES / 8, 256>>>(z, batch, bm, Wa1, ba1, Wh, bh, bo, out);
    k2_final<<<(B * M * E + 255) / 256, 256>>>(mv, wm, bm, out);
}